// round 2
// baseline (speedup 1.0000x reference)
#include <cuda_runtime.h>

// Point_Transformer fused kernel for sm_100a.
// B=8, N=8192, K=10, channels=64. One warp per (b,n) point; lane owns 2 channels.
// Persistent blocks; all weights resident in shared memory (transposed).
// ptf collapsed algebraically: ptf[o,k] = ptsn[k] * M[o], M = Wp2 @ relu(Wp1)
// (valid because ptsn = sum-of-squares >= 0).

#define NB 8
#define NN 8192
#define NKK 10
#define NTILE 4096      // (B*N)/16 point-tiles
#define WARPS 16
#define THREADS 512
#define GRID 148

typedef unsigned long long ull;

__device__ __forceinline__ ull pk2(float lo, float hi) {
    ull r; asm("mov.b64 %0,{%1,%2};" : "=l"(r) : "f"(lo), "f"(hi)); return r;
}
__device__ __forceinline__ void upk(ull v, float& lo, float& hi) {
    asm("mov.b64 {%0,%1},%2;" : "=f"(lo), "=f"(hi) : "l"(v));
}
__device__ __forceinline__ void f2(ull& d, ull a, ull b) {
    asm("fma.rn.f32x2 %0,%1,%2,%0;" : "+l"(d) : "l"(a), "l"(b));
}

struct __align__(16) Smem {
    float W0t[4096];           // [c][o] transposed
    float W1t[4096];
    float W2t[4096];
    float W3t[4096];
    float Wot[4096];
    float Ww1[5120];           // [8][640] as-is
    float Ww2[640];            // [80][8] as-is
    float Mv[64];              // Wp2 @ relu(Wp1)
    float b0[64], b1[64], b2[64], b3[64], bo[64];
    float bw2[80];
    float buf[WARPS][768];     // 64 rows x 12 (padded) floats; feats -> xn -> xfs
    float pbuf[WARPS][16];     // ptsn per k
    float wvb[WARPS][80];      // gate logits / softmax weights
    float opre[WARPS][64];     // pre-output vector
    float stg[64 * 17];        // output staging [o][16 warps + pad]
};

__global__ void __launch_bounds__(THREADS, 1)
pt_kernel(const float* __restrict__ gF,   // sm_feats (B,64,N,K)
          const float* __restrict__ gC,   // cent_pts (B,N,3)
          const float* __restrict__ gP,   // sm_pts   (B,3,N,K)
          const float* __restrict__ gW0, const float* __restrict__ gb0,
          const float* __restrict__ gW1, const float* __restrict__ gb1,
          const float* __restrict__ gW2, const float* __restrict__ gb2,
          const float* __restrict__ gW3, const float* __restrict__ gb3,
          const float* __restrict__ gWp1, const float* __restrict__ gWp2,
          const float* __restrict__ gWw1, const float* __restrict__ gWw2,
          const float* __restrict__ gbw2,
          const float* __restrict__ gWo, const float* __restrict__ gbo,
          float* __restrict__ gOut)
{
    extern __shared__ char raw[];
    Smem& S = *reinterpret_cast<Smem*>(raw);
    const int tid = threadIdx.x, lane = tid & 31, wid = tid >> 5;

    // ---- one-time per-block weight staging ----
    for (int i = tid; i < 4096; i += THREADS) {
        int o = i >> 6, c = i & 63;
        int tix = c * 64 + o;
        S.W0t[tix] = gW0[i];
        S.W1t[tix] = gW1[i];
        S.W2t[tix] = gW2[i];
        S.W3t[tix] = gW3[i];
        S.Wot[tix] = gWo[i];
    }
    for (int i = tid; i < 5120; i += THREADS) S.Ww1[i] = gWw1[i];
    for (int i = tid; i < 640;  i += THREADS) S.Ww2[i] = gWw2[i];
    if (tid < 64) {
        float m = 0.f;
        #pragma unroll 8
        for (int c = 0; c < 64; ++c) m += gWp2[tid * 64 + c] * fmaxf(gWp1[c], 0.f);
        S.Mv[tid] = m;
        S.b0[tid] = gb0[tid]; S.b1[tid] = gb1[tid]; S.b2[tid] = gb2[tid];
        S.b3[tid] = gb3[tid]; S.bo[tid] = gbo[tid];
    }
    if (tid >= 64 && tid < 144) S.bw2[tid - 64] = gbw2[tid - 64];
    __syncthreads();

    const int o0 = lane * 2, o1 = o0 + 1;
    float* buf = S.buf[wid];
    float* pb  = S.pbuf[wid];
    float* wvb = S.wvb[wid];
    float* op  = S.opre[wid];

    for (int t = blockIdx.x; t < NTILE; t += gridDim.x) {
        const int p = t * 16 + wid;
        const int b = p >> 13;
        const int n = p & (NN - 1);

        // ---- load feats (64 x 10) into padded smem rows ----
        {
            const float* fp = gF + (size_t)b * (64 * NN * NKK) + (size_t)n * NKK;
            #pragma unroll
            for (int i = lane; i < 640; i += 32) {
                int c = i / 10, kk = i - c * 10;
                buf[c * 12 + kk] = fp[(size_t)c * (NN * NKK) + kk];
            }
        }
        // ---- ptsn[k] (lanes 0..9) ----
        if (lane < 10) {
            const float* cp = gC + ((size_t)b * NN + n) * 3;
            float cx = cp[0], cy = cp[1], cz = cp[2];
            const float* pp = gP + (size_t)b * (3 * NN * NKK) + (size_t)n * NKK + lane;
            float dx = cx - pp[0];
            float dy = cy - pp[NN * NKK];
            float dz = cz - pp[2 * NN * NKK];
            pb[lane] = dx * dx + dy * dy + dz * dz;
        }
        __syncwarp();

        // ---- xn = relu(W0 @ feats + b0), packed over k-pairs ----
        ull xa[5], xbq[5];
        {
            ull i0 = pk2(S.b0[o0], S.b0[o0]);
            ull i1 = pk2(S.b0[o1], S.b0[o1]);
            #pragma unroll
            for (int q = 0; q < 5; q++) { xa[q] = i0; xbq[q] = i1; }
        }
        #pragma unroll 4
        for (int c = 0; c < 64; c++) {
            const float* row = buf + c * 12;
            float4 r0 = *(const float4*)(row);
            float4 r1 = *(const float4*)(row + 4);
            float2 r2 = *(const float2*)(row + 8);
            ull xp[5] = { pk2(r0.x, r0.y), pk2(r0.z, r0.w),
                          pk2(r1.x, r1.y), pk2(r1.z, r1.w), pk2(r2.x, r2.y) };
            float2 w0 = *(const float2*)(S.W0t + c * 64 + o0);
            ull wa = pk2(w0.x, w0.x), wb = pk2(w0.y, w0.y);
            #pragma unroll
            for (int q = 0; q < 5; q++) { f2(xa[q], wa, xp[q]); f2(xbq[q], wb, xp[q]); }
        }
        float xn0[10], xn1[10];
        #pragma unroll
        for (int q = 0; q < 5; q++) {
            upk(xa[q],  xn0[2 * q], xn0[2 * q + 1]);
            upk(xbq[q], xn1[2 * q], xn1[2 * q + 1]);
        }
        #pragma unroll
        for (int k = 0; k < 10; k++) { xn0[k] = fmaxf(xn0[k], 0.f); xn1[k] = fmaxf(xn1[k], 0.f); }
        __syncwarp();   // all lanes done reading feats
        *(float4*)(buf + o0 * 12)     = make_float4(xn0[0], xn0[1], xn0[2], xn0[3]);
        *(float4*)(buf + o0 * 12 + 4) = make_float4(xn0[4], xn0[5], xn0[6], xn0[7]);
        *(float2*)(buf + o0 * 12 + 8) = make_float2(xn0[8], xn0[9]);
        *(float4*)(buf + o1 * 12)     = make_float4(xn1[0], xn1[1], xn1[2], xn1[3]);
        *(float4*)(buf + o1 * 12 + 4) = make_float4(xn1[4], xn1[5], xn1[6], xn1[7]);
        *(float2*)(buf + o1 * 12 + 8) = make_float2(xn1[8], xn1[9]);
        __syncwarp();

        const float x00 = xn0[0], x01v = xn1[0];   // x = xn[:, k=0]
        float pk_[10];
        #pragma unroll
        for (int k = 0; k < 10; k++) pk_[k] = pb[k];

        // ---- main matvecs: x1 (k=0 only), x2, x3 over xn ----
        ull a2a[5], a2b[5], a3a[5], a3b[5], a1a, a1b;
        {
            ull i2a = pk2(S.b2[o0], S.b2[o0]), i2b = pk2(S.b2[o1], S.b2[o1]);
            ull i3a = pk2(S.b3[o0], S.b3[o0]), i3b = pk2(S.b3[o1], S.b3[o1]);
            #pragma unroll
            for (int q = 0; q < 5; q++) { a2a[q] = i2a; a2b[q] = i2b; a3a[q] = i3a; a3b[q] = i3b; }
            a1a = pk2(S.b1[o0], 0.f);
            a1b = pk2(S.b1[o1], 0.f);
        }
        #pragma unroll 4
        for (int c = 0; c < 64; c++) {
            const float* row = buf + c * 12;
            float4 r0 = *(const float4*)(row);
            float4 r1 = *(const float4*)(row + 4);
            float2 r2 = *(const float2*)(row + 8);
            ull xp[5] = { pk2(r0.x, r0.y), pk2(r0.z, r0.w),
                          pk2(r1.x, r1.y), pk2(r1.z, r1.w), pk2(r2.x, r2.y) };
            float2 w1 = *(const float2*)(S.W1t + c * 64 + o0);
            float2 w2 = *(const float2*)(S.W2t + c * 64 + o0);
            float2 w3 = *(const float2*)(S.W3t + c * 64 + o0);
            ull w2a = pk2(w2.x, w2.x), w2b = pk2(w2.y, w2.y);
            ull w3a = pk2(w3.x, w3.x), w3b = pk2(w3.y, w3.y);
            #pragma unroll
            for (int q = 0; q < 5; q++) {
                f2(a2a[q], w2a, xp[q]); f2(a2b[q], w2b, xp[q]);
                f2(a3a[q], w3a, xp[q]); f2(a3b[q], w3b, xp[q]);
            }
            f2(a1a, pk2(w1.x, 0.f), xp[0]);
            f2(a1b, pk2(w1.y, 0.f), xp[0]);
        }

        // ---- epilogue: x3f = x3 + ptf, xfs = x1 - x2 + ptf ----
        float x1v0, x1v1, junk;
        upk(a1a, x1v0, junk);
        upk(a1b, x1v1, junk);
        const float M0 = S.Mv[o0], M1 = S.Mv[o1];
        float x3f0[10], x3f1[10], xf0[10], xf1[10];
        #pragma unroll
        for (int q = 0; q < 5; q++) {
            float u0, u1, v0, v1;
            int k0 = 2 * q, k1 = 2 * q + 1;
            float pt0a = pk_[k0] * M0, pt1a = pk_[k1] * M0;
            float pt0b = pk_[k0] * M1, pt1b = pk_[k1] * M1;
            upk(a2a[q], u0, u1); upk(a3a[q], v0, v1);
            x3f0[k0] = v0 + pt0a;           x3f0[k1] = v1 + pt1a;
            xf0[k0]  = x1v0 - u0 + pt0a;    xf0[k1]  = x1v0 - u1 + pt1a;
            upk(a2b[q], u0, u1); upk(a3b[q], v0, v1);
            x3f1[k0] = v0 + pt0b;           x3f1[k1] = v1 + pt1b;
            xf1[k0]  = x1v1 - u0 + pt0b;    xf1[k1]  = x1v1 - u1 + pt1b;
        }
        __syncwarp();   // all lanes done reading xn from buf
        // store xfs flat at m = o*10 + k  (lane's 20 values contiguous at 20*lane)
        {
            float* xb = buf + 20 * lane;
            *(float4*)(xb)      = make_float4(xf0[0], xf0[1], xf0[2], xf0[3]);
            *(float4*)(xb + 4)  = make_float4(xf0[4], xf0[5], xf0[6], xf0[7]);
            *(float2*)(xb + 8)  = make_float2(xf0[8], xf0[9]);
            *(float2*)(xb + 10) = make_float2(xf1[0], xf1[1]);
            *(float4*)(xb + 12) = make_float4(xf1[2], xf1[3], xf1[4], xf1[5]);
            *(float4*)(xb + 16) = make_float4(xf1[6], xf1[7], xf1[8], xf1[9]);
        }
        __syncwarp();

        // ---- h = relu(Ww1 @ xfs) : lane-strided conflict-free accumulation ----
        float hp[8] = {0.f, 0.f, 0.f, 0.f, 0.f, 0.f, 0.f, 0.f};
        #pragma unroll 4
        for (int tt = 0; tt < 20; tt++) {
            int m = lane + tt * 32;
            float xv = buf[m];
            #pragma unroll
            for (int j = 0; j < 8; j++) hp[j] += S.Ww1[j * 640 + m] * xv;
        }
        #pragma unroll
        for (int j = 0; j < 8; j++) {
            float v = hp[j];
            v += __shfl_xor_sync(0xffffffffu, v, 16);
            v += __shfl_xor_sync(0xffffffffu, v, 8);
            v += __shfl_xor_sync(0xffffffffu, v, 4);
            v += __shfl_xor_sync(0xffffffffu, v, 2);
            v += __shfl_xor_sync(0xffffffffu, v, 1);
            hp[j] = fmaxf(v, 0.f);
        }
        // ---- wv logits + softmax over k ----
        for (int r = lane; r < 80; r += 32) {
            float v = S.bw2[r];
            #pragma unroll
            for (int j = 0; j < 8; j++) v += S.Ww2[r * 8 + j] * hp[j];
            wvb[r] = v;
        }
        __syncwarp();
        if (lane < 8) {
            float* wr = wvb + lane * 10;
            float mx = wr[0];
            #pragma unroll
            for (int k = 1; k < 10; k++) mx = fmaxf(mx, wr[k]);
            float e[10]; float sum = 0.f;
            #pragma unroll
            for (int k = 0; k < 10; k++) { e[k] = __expf(wr[k] - mx); sum += e[k]; }
            float inv = 1.f / sum;
            #pragma unroll
            for (int k = 0; k < 10; k++) wr[k] = e[k] * inv;
        }
        __syncwarp();

        // ---- out_pre[c] = relu(sum_k w[c%8][k] * x3f[c][k]) ----
        {
            int g0 = o0 & 7;
            float s0 = 0.f, s1 = 0.f;
            #pragma unroll
            for (int k = 0; k < 10; k++) {
                s0 += wvb[g0 * 10 + k] * x3f0[k];
                s1 += wvb[(g0 + 1) * 10 + k] * x3f1[k];
            }
            *(float2*)(op + o0) = make_float2(fmaxf(s0, 0.f), fmaxf(s1, 0.f));
        }
        __syncwarp();

        // ---- final = Wout @ out_pre + bout + x ----
        ull acc = pk2(S.bo[o0] + x00, S.bo[o1] + x01v);
        #pragma unroll 8
        for (int c = 0; c < 64; c++) {
            float ov = op[c];
            ull wo = *(const ull*)(S.Wot + c * 64 + o0);
            f2(acc, wo, pk2(ov, ov));
        }
        float f0, f1v;
        upk(acc, f0, f1v);

        __syncthreads();                       // prior tile's staged stores fully read
        S.stg[o0 * 17 + wid] = f0;
        S.stg[o1 * 17 + wid] = f1v;
        __syncthreads();
        {
            const int p0 = t * 16;
            const int bb = p0 >> 13;
            const int n0 = p0 & (NN - 1);
            float* ob = gOut + (size_t)bb * 64 * NN + n0;
            #pragma unroll
            for (int i = tid; i < 1024; i += THREADS) {
                int o = i >> 4, j = i & 15;
                ob[(size_t)o * NN + j] = S.stg[o * 17 + j];
            }
        }
    }
}

extern "C" void kernel_launch(void* const* d_in, const int* in_sizes, int n_in,
                              void* d_out, int out_size) {
    (void)in_sizes; (void)n_in; (void)out_size;
    cudaFuncSetAttribute(pt_kernel, cudaFuncAttributeMaxDynamicSharedMemorySize,
                         (int)sizeof(Smem));
    pt_kernel<<<GRID, THREADS, sizeof(Smem)>>>(
        (const float*)d_in[0],  (const float*)d_in[1],  (const float*)d_in[2],
        (const float*)d_in[3],  (const float*)d_in[4],
        (const float*)d_in[5],  (const float*)d_in[6],
        (const float*)d_in[7],  (const float*)d_in[8],
        (const float*)d_in[9],  (const float*)d_in[10],
        (const float*)d_in[11], (const float*)d_in[12],
        (const float*)d_in[13], (const float*)d_in[14], (const float*)d_in[15],
        (const float*)d_in[16], (const float*)d_in[17],
        (float*)d_out);
}

// round 5
// speedup vs baseline: 1.0509x; 1.0509x over previous
#include <cuda_runtime.h>

// Point_Transformer fused kernel for sm_100a — round 3 design (3rd submit; broker failed twice).
// 2 points per warp (weight-smem amortization); x3 matvec eliminated via
// gating algebra: sum_k wv*x3f = W3 @ y + b3 + M*pg,  y[cin,g]=sum_k wv[g,k]*xn[cin,k].

#define NN 8192
#define NKK 10
#define WARPS 16
#define THREADS 512
#define GRID 148
#define NTILE 2048      // 65536 points / 32 per block-tile

typedef unsigned long long ull;

__device__ __forceinline__ ull pk2(float lo, float hi) {
    ull r; asm("mov.b64 %0,{%1,%2};" : "=l"(r) : "f"(lo), "f"(hi)); return r;
}
__device__ __forceinline__ void upk(ull v, float& lo, float& hi) {
    asm("mov.b64 {%0,%1},%2;" : "=f"(lo), "=f"(hi) : "l"(v));
}
__device__ __forceinline__ void f2(ull& d, ull a, ull b) {
    asm("fma.rn.f32x2 %0,%1,%2,%0;" : "+l"(d) : "l"(a), "l"(b));
}

struct __align__(16) Smem {
    float W0t[4096];           // [cin][cout]
    float W1t[4096];
    float W2t[4096];
    float W3t[4096];
    float Wot[4096];
    float Ww1[5120];           // [8][640]
    float Ww2[640];            // [80][8]
    float Mv[64];              // Wp2 @ relu(Wp1)
    float b0[64], b1[64], b2[64], b3[64], bo[64];
    float bw2[80];
    float buf[WARPS][2][768];  // per point: feats/xn rows (12-pad) -> xfs flat -> y (10-pad) -> op
    float pbuf[WARPS][2][16];  // ptsn
    float wvb[WARPS][2][96];   // softmax weights, rows padded to 12
    float stg[64 * 34];        // output staging
};

__global__ void __launch_bounds__(THREADS, 1)
pt_kernel(const float* __restrict__ gF,   // sm_feats (B,64,N,K)
          const float* __restrict__ gC,   // cent_pts (B,N,3)
          const float* __restrict__ gP,   // sm_pts   (B,3,N,K)
          const float* __restrict__ gW0, const float* __restrict__ gb0,
          const float* __restrict__ gW1, const float* __restrict__ gb1,
          const float* __restrict__ gW2, const float* __restrict__ gb2,
          const float* __restrict__ gW3, const float* __restrict__ gb3,
          const float* __restrict__ gWp1, const float* __restrict__ gWp2,
          const float* __restrict__ gWw1, const float* __restrict__ gWw2,
          const float* __restrict__ gbw2,
          const float* __restrict__ gWo, const float* __restrict__ gbo,
          float* __restrict__ gOut)
{
    extern __shared__ char raw[];
    Smem& S = *reinterpret_cast<Smem*>(raw);
    const int tid = threadIdx.x, lane = tid & 31, wid = tid >> 5;

    // ---- one-time weight staging ----
    for (int i = tid; i < 4096; i += THREADS) {
        int o = i >> 6, c = i & 63;
        int tix = c * 64 + o;
        S.W0t[tix] = gW0[i];
        S.W1t[tix] = gW1[i];
        S.W2t[tix] = gW2[i];
        S.W3t[tix] = gW3[i];
        S.Wot[tix] = gWo[i];
    }
    for (int i = tid; i < 5120; i += THREADS) S.Ww1[i] = gWw1[i];
    for (int i = tid; i < 640;  i += THREADS) S.Ww2[i] = gWw2[i];
    if (tid < 64) {
        float m = 0.f;
        #pragma unroll 8
        for (int c = 0; c < 64; ++c) m += gWp2[tid * 64 + c] * fmaxf(gWp1[c], 0.f);
        S.Mv[tid] = m;
        S.b0[tid] = gb0[tid]; S.b1[tid] = gb1[tid]; S.b2[tid] = gb2[tid];
        S.b3[tid] = gb3[tid]; S.bo[tid] = gbo[tid];
    }
    if (tid >= 64 && tid < 144) S.bw2[tid - 64] = gbw2[tid - 64];
    __syncthreads();

    const int o0 = lane * 2, o1 = o0 + 1;
    const int g0 = o0 & 7;
    float* bufA = S.buf[wid][0];
    float* bufB = S.buf[wid][1];

    for (int t = blockIdx.x; t < NTILE; t += GRID) {
        const int p0 = t * 32;
        const int b  = p0 >> 13;
        const int n0 = p0 & (NN - 1);
        const int n  = n0 + wid * 2;          // this warp: points n, n+1 (same b)

        // ---- feats load: 64 rows x 20 floats (both points interleaved in gmem) ----
        {
            const float* fp = gF + (size_t)b * (64 * NN * NKK) + (size_t)n * NKK;
            #pragma unroll
            for (int i = lane; i < 1280; i += 32) {
                int c = i / 20, r = i - c * 20, ip = r / 10, k = r - ip * 10;
                S.buf[wid][ip][c * 12 + k] = fp[(size_t)c * (NN * NKK) + r];
            }
        }
        // ---- ptsn: lanes 0-9 point0, lanes 16-25 point1 ----
        if ((lane & 15) < 10 && lane < 26) {
            int ip = lane >> 4, k = lane & 15;
            const float* cp = gC + ((size_t)b * NN + n + ip) * 3;
            const float* pp = gP + (size_t)b * (3 * NN * NKK) + (size_t)(n + ip) * NKK + k;
            float dx = cp[0] - pp[0];
            float dy = cp[1] - pp[NN * NKK];
            float dz = cp[2] - pp[2 * NN * NKK];
            S.pbuf[wid][ip][k] = dx * dx + dy * dy + dz * dz;
        }
        __syncwarp();

        // ================= Phase 1: xn = relu(W0 @ feats + b0), both points =================
        ull xacc[2][2][5];
        {
            ull i0 = pk2(S.b0[o0], S.b0[o0]);
            ull i1 = pk2(S.b0[o1], S.b0[o1]);
            #pragma unroll
            for (int q = 0; q < 5; q++) {
                xacc[0][0][q] = i0; xacc[0][1][q] = i1;
                xacc[1][0][q] = i0; xacc[1][1][q] = i1;
            }
        }
        #pragma unroll 2
        for (int c = 0; c < 64; c++) {
            ull xp[2][5];
            #pragma unroll
            for (int ip = 0; ip < 2; ip++) {
                const float* row = S.buf[wid][ip] + c * 12;
                float4 r0 = *(const float4*)(row);
                float4 r1 = *(const float4*)(row + 4);
                float2 r2 = *(const float2*)(row + 8);
                xp[ip][0] = pk2(r0.x, r0.y); xp[ip][1] = pk2(r0.z, r0.w);
                xp[ip][2] = pk2(r1.x, r1.y); xp[ip][3] = pk2(r1.z, r1.w);
                xp[ip][4] = pk2(r2.x, r2.y);
            }
            float2 w0 = *(const float2*)(S.W0t + c * 64 + o0);
            ull wa = pk2(w0.x, w0.x), wb = pk2(w0.y, w0.y);
            #pragma unroll
            for (int ip = 0; ip < 2; ip++)
                #pragma unroll
                for (int q = 0; q < 5; q++) {
                    f2(xacc[ip][0][q], wa, xp[ip][q]);
                    f2(xacc[ip][1][q], wb, xp[ip][q]);
                }
        }
        float xnv[2][2][10];
        #pragma unroll
        for (int ip = 0; ip < 2; ip++)
            #pragma unroll
            for (int q = 0; q < 5; q++) {
                upk(xacc[ip][0][q], xnv[ip][0][2 * q], xnv[ip][0][2 * q + 1]);
                upk(xacc[ip][1][q], xnv[ip][1][2 * q], xnv[ip][1][2 * q + 1]);
            }
        #pragma unroll
        for (int ip = 0; ip < 2; ip++)
            #pragma unroll
            for (int ch = 0; ch < 2; ch++)
                #pragma unroll
                for (int k = 0; k < 10; k++)
                    xnv[ip][ch][k] = fmaxf(xnv[ip][ch][k], 0.f);
        __syncwarp();   // done reading feats
        #pragma unroll
        for (int ip = 0; ip < 2; ip++) {
            float* base = S.buf[wid][ip];
            *(float4*)(base + o0 * 12)     = make_float4(xnv[ip][0][0], xnv[ip][0][1], xnv[ip][0][2], xnv[ip][0][3]);
            *(float4*)(base + o0 * 12 + 4) = make_float4(xnv[ip][0][4], xnv[ip][0][5], xnv[ip][0][6], xnv[ip][0][7]);
            *(float2*)(base + o0 * 12 + 8) = make_float2(xnv[ip][0][8], xnv[ip][0][9]);
            *(float4*)(base + o1 * 12)     = make_float4(xnv[ip][1][0], xnv[ip][1][1], xnv[ip][1][2], xnv[ip][1][3]);
            *(float4*)(base + o1 * 12 + 4) = make_float4(xnv[ip][1][4], xnv[ip][1][5], xnv[ip][1][6], xnv[ip][1][7]);
            *(float2*)(base + o1 * 12 + 8) = make_float2(xnv[ip][1][8], xnv[ip][1][9]);
        }
        __syncwarp();
        float x0res[2][2];
        x0res[0][0] = xnv[0][0][0]; x0res[0][1] = xnv[0][1][0];
        x0res[1][0] = xnv[1][0][0]; x0res[1][1] = xnv[1][1][0];

        // ================= Phase 2: x1 (k=0) and x2, both points =================
        ull a2[2][2][5], a1[2];
        {
            ull i2a = pk2(S.b2[o0], S.b2[o0]);
            ull i2b = pk2(S.b2[o1], S.b2[o1]);
            #pragma unroll
            for (int q = 0; q < 5; q++) {
                a2[0][0][q] = i2a; a2[0][1][q] = i2b;
                a2[1][0][q] = i2a; a2[1][1][q] = i2b;
            }
            ull i1 = pk2(S.b1[o0], S.b1[o1]);
            a1[0] = i1; a1[1] = i1;
        }
        #pragma unroll 1
        for (int c = 0; c < 64; c++) {
            ull xp[2][5]; float xk0[2];
            #pragma unroll
            for (int ip = 0; ip < 2; ip++) {
                const float* row = S.buf[wid][ip] + c * 12;
                float4 r0 = *(const float4*)(row);
                float4 r1 = *(const float4*)(row + 4);
                float2 r2 = *(const float2*)(row + 8);
                xp[ip][0] = pk2(r0.x, r0.y); xp[ip][1] = pk2(r0.z, r0.w);
                xp[ip][2] = pk2(r1.x, r1.y); xp[ip][3] = pk2(r1.z, r1.w);
                xp[ip][4] = pk2(r2.x, r2.y);
                xk0[ip] = r0.x;
            }
            float2 w1 = *(const float2*)(S.W1t + c * 64 + o0);
            float2 w2 = *(const float2*)(S.W2t + c * 64 + o0);
            ull w2a = pk2(w2.x, w2.x), w2b = pk2(w2.y, w2.y);
            ull w1p = pk2(w1.x, w1.y);
            #pragma unroll
            for (int ip = 0; ip < 2; ip++) {
                #pragma unroll
                for (int q = 0; q < 5; q++) {
                    f2(a2[ip][0][q], w2a, xp[ip][q]);
                    f2(a2[ip][1][q], w2b, xp[ip][q]);
                }
                f2(a1[ip], w1p, pk2(xk0[ip], xk0[ip]));
            }
        }

        // ---- epilogue: xf = x1 - x2 + ptsn*M ----
        const float M0 = S.Mv[o0], M1 = S.Mv[o1];
        float xf[2][2][10];
        #pragma unroll
        for (int ip = 0; ip < 2; ip++) {
            float x1lo, x1hi; upk(a1[ip], x1lo, x1hi);
            const float* pb = S.pbuf[wid][ip];
            #pragma unroll
            for (int q = 0; q < 5; q++) {
                float pt0 = pb[2 * q] ;
                float pt1 = pb[2 * q + 1];
                float u0, u1;
                upk(a2[ip][0][q], u0, u1);
                xf[ip][0][2 * q]     = x1lo - u0 + pt0 * M0;
                xf[ip][0][2 * q + 1] = x1lo - u1 + pt1 * M0;
                upk(a2[ip][1][q], u0, u1);
                xf[ip][1][2 * q]     = x1hi - u0 + pt0 * M1;
                xf[ip][1][2 * q + 1] = x1hi - u1 + pt1 * M1;
            }
        }
        // re-read own xn rows into regs (needed for y after softmax; buf gets overwritten)
        float xn[2][2][10];
        #pragma unroll
        for (int ip = 0; ip < 2; ip++) {
            const float* base = S.buf[wid][ip];
            float4 a0 = *(const float4*)(base + o0 * 12);
            float4 a1v = *(const float4*)(base + o0 * 12 + 4);
            float2 a2v = *(const float2*)(base + o0 * 12 + 8);
            xn[ip][0][0] = a0.x; xn[ip][0][1] = a0.y; xn[ip][0][2] = a0.z; xn[ip][0][3] = a0.w;
            xn[ip][0][4] = a1v.x; xn[ip][0][5] = a1v.y; xn[ip][0][6] = a1v.z; xn[ip][0][7] = a1v.w;
            xn[ip][0][8] = a2v.x; xn[ip][0][9] = a2v.y;
            float4 b0v = *(const float4*)(base + o1 * 12);
            float4 b1v = *(const float4*)(base + o1 * 12 + 4);
            float2 b2v = *(const float2*)(base + o1 * 12 + 8);
            xn[ip][1][0] = b0v.x; xn[ip][1][1] = b0v.y; xn[ip][1][2] = b0v.z; xn[ip][1][3] = b0v.w;
            xn[ip][1][4] = b1v.x; xn[ip][1][5] = b1v.y; xn[ip][1][6] = b1v.z; xn[ip][1][7] = b1v.w;
            xn[ip][1][8] = b2v.x; xn[ip][1][9] = b2v.y;
        }
        __syncwarp();
        // store xfs flat: m = o*10 + k  -> lane region [20*lane, 20*lane+20)
        #pragma unroll
        for (int ip = 0; ip < 2; ip++) {
            float* xb = S.buf[wid][ip] + 20 * lane;
            *(float4*)(xb)      = make_float4(xf[ip][0][0], xf[ip][0][1], xf[ip][0][2], xf[ip][0][3]);
            *(float4*)(xb + 4)  = make_float4(xf[ip][0][4], xf[ip][0][5], xf[ip][0][6], xf[ip][0][7]);
            *(float2*)(xb + 8)  = make_float2(xf[ip][0][8], xf[ip][0][9]);
            *(float2*)(xb + 10) = make_float2(xf[ip][1][0], xf[ip][1][1]);
            *(float4*)(xb + 12) = make_float4(xf[ip][1][2], xf[ip][1][3], xf[ip][1][4], xf[ip][1][5]);
            *(float4*)(xb + 16) = make_float4(xf[ip][1][6], xf[ip][1][7], xf[ip][1][8], xf[ip][1][9]);
        }
        __syncwarp();

        // ================= h = relu(Ww1 @ xfs), shared Ww1 loads =================
        float h[2][8];
        #pragma unroll
        for (int j = 0; j < 8; j++) { h[0][j] = 0.f; h[1][j] = 0.f; }
        #pragma unroll 4
        for (int tt = 0; tt < 20; tt++) {
            int m = lane + tt * 32;
            float fA = bufA[m], fB = bufB[m];
            #pragma unroll
            for (int j = 0; j < 8; j++) {
                float w = S.Ww1[j * 640 + m];
                h[0][j] += w * fA;
                h[1][j] += w * fB;
            }
        }
        #pragma unroll
        for (int ip = 0; ip < 2; ip++)
            #pragma unroll
            for (int j = 0; j < 8; j++) {
                float v = h[ip][j];
                v += __shfl_xor_sync(0xffffffffu, v, 16);
                v += __shfl_xor_sync(0xffffffffu, v, 8);
                v += __shfl_xor_sync(0xffffffffu, v, 4);
                v += __shfl_xor_sync(0xffffffffu, v, 2);
                v += __shfl_xor_sync(0xffffffffu, v, 1);
                h[ip][j] = fmaxf(v, 0.f);
            }
        // ---- logits -> wvb (rows padded to 12) ----
        #pragma unroll
        for (int ip = 0; ip < 2; ip++) {
            float* wv = S.wvb[wid][ip];
            #pragma unroll
            for (int r = lane; r < 80; r += 32) {
                float v = S.bw2[r];
                #pragma unroll
                for (int j = 0; j < 8; j++) v += S.Ww2[r * 8 + j] * h[ip][j];
                int g = r / 10, k = r - g * 10;
                wv[g * 12 + k] = v;
            }
        }
        __syncwarp();
        // ---- softmax over k: lanes 0-7 point0, lanes 16-23 point1 ----
        if ((lane & 15) < 8 && lane < 24) {
            int ip = lane >> 4, g = lane & 15;
            float* wr = S.wvb[wid][ip] + g * 12;
            float mx = wr[0];
            #pragma unroll
            for (int k = 1; k < 10; k++) mx = fmaxf(mx, wr[k]);
            float e[10]; float sum = 0.f;
            #pragma unroll
            for (int k = 0; k < 10; k++) { e[k] = __expf(wr[k] - mx); sum += e[k]; }
            float inv = 1.f / sum;
            #pragma unroll
            for (int k = 0; k < 10; k++) wr[k] = e[k] * inv;
        }
        __syncwarp();

        // ================= y[cin][g] = sum_k wv[g,k]*xn[cin,k]  (overwrites xfs) =================
        #pragma unroll
        for (int ip = 0; ip < 2; ip++) {
            const float* wv = S.wvb[wid][ip];
            float y0[8], y1[8];
            #pragma unroll
            for (int g = 0; g < 8; g++) {
                const float* wr = wv + g * 12;
                float4 w0q = *(const float4*)(wr);
                float4 w1q = *(const float4*)(wr + 4);
                float2 w2q = *(const float2*)(wr + 8);
                float s0 = w0q.x * xn[ip][0][0] + w0q.y * xn[ip][0][1] + w0q.z * xn[ip][0][2] + w0q.w * xn[ip][0][3]
                         + w1q.x * xn[ip][0][4] + w1q.y * xn[ip][0][5] + w1q.z * xn[ip][0][6] + w1q.w * xn[ip][0][7]
                         + w2q.x * xn[ip][0][8] + w2q.y * xn[ip][0][9];
                float s1 = w0q.x * xn[ip][1][0] + w0q.y * xn[ip][1][1] + w0q.z * xn[ip][1][2] + w0q.w * xn[ip][1][3]
                         + w1q.x * xn[ip][1][4] + w1q.y * xn[ip][1][5] + w1q.z * xn[ip][1][6] + w1q.w * xn[ip][1][7]
                         + w2q.x * xn[ip][1][8] + w2q.y * xn[ip][1][9];
                y0[g] = s0; y1[g] = s1;
            }
            float* yb = S.buf[wid][ip];      // y row stride 10: y[cin*10+g]
            *(float4*)(yb + o0 * 10)     = make_float4(y0[0], y0[1], y0[2], y0[3]);
            *(float4*)(yb + o0 * 10 + 4) = make_float4(y0[4], y0[5], y0[6], y0[7]);
            *(float2*)(yb + o1 * 10)     = make_float2(y1[0], y1[1]);
            *(float2*)(yb + o1 * 10 + 2) = make_float2(y1[2], y1[3]);
            *(float2*)(yb + o1 * 10 + 4) = make_float2(y1[4], y1[5]);
            *(float2*)(yb + o1 * 10 + 6) = make_float2(y1[6], y1[7]);
        }
        __syncwarp();

        // ---- pg[g] = sum_k wv[g,k]*ptsn[k] for this lane's g0,g0+1 ----
        float pg[2][2];
        #pragma unroll
        for (int ip = 0; ip < 2; ip++) {
            const float* wv = S.wvb[wid][ip];
            const float* pb = S.pbuf[wid][ip];
            float s0 = 0.f, s1 = 0.f;
            #pragma unroll
            for (int k = 0; k < 10; k++) {
                float pv = pb[k];
                s0 += wv[g0 * 12 + k] * pv;
                s1 += wv[(g0 + 1) * 12 + k] * pv;
            }
            pg[ip][0] = s0; pg[ip][1] = s1;
        }

        // ================= s[c] = sum_cin W3[c,cin]*y[cin,g(c)]; op = relu(s+b3+M*pg) ===========
        ull sacc[2];
        sacc[0] = pk2(0.f, 0.f); sacc[1] = pk2(0.f, 0.f);
        #pragma unroll 4
        for (int cin = 0; cin < 64; cin++) {
            ull w = *(const ull*)(S.W3t + cin * 64 + o0);
            float2 ya = *(const float2*)(bufA + cin * 10 + g0);
            float2 yb2 = *(const float2*)(bufB + cin * 10 + g0);
            f2(sacc[0], w, pk2(ya.x, ya.y));
            f2(sacc[1], w, pk2(yb2.x, yb2.y));
        }
        __syncwarp();
        #pragma unroll
        for (int ip = 0; ip < 2; ip++) {
            float slo, shi; upk(sacc[ip], slo, shi);
            float v0 = fmaxf(slo + S.b3[o0] + M0 * pg[ip][0], 0.f);
            float v1 = fmaxf(shi + S.b3[o1] + M1 * pg[ip][1], 0.f);
            *(float2*)(S.buf[wid][ip] + o0) = make_float2(v0, v1);   // op at [0,64)
        }
        __syncwarp();

        // ================= final = Wout @ op + bout + x =================
        ull acc[2];
        acc[0] = pk2(S.bo[o0] + x0res[0][0], S.bo[o1] + x0res[0][1]);
        acc[1] = pk2(S.bo[o0] + x0res[1][0], S.bo[o1] + x0res[1][1]);
        #pragma unroll 8
        for (int c = 0; c < 64; c++) {
            ull w = *(const ull*)(S.Wot + c * 64 + o0);
            float ovA = bufA[c], ovB = bufB[c];
            f2(acc[0], w, pk2(ovA, ovA));
            f2(acc[1], w, pk2(ovB, ovB));
        }
        float fA0, fA1, fB0, fB1;
        upk(acc[0], fA0, fA1);
        upk(acc[1], fB0, fB1);

        __syncthreads();                 // prior tile's staged stores fully consumed
        S.stg[o0 * 34 + wid * 2]     = fA0;
        S.stg[o1 * 34 + wid * 2]     = fA1;
        S.stg[o0 * 34 + wid * 2 + 1] = fB0;
        S.stg[o1 * 34 + wid * 2 + 1] = fB1;
        __syncthreads();
        {
            float* ob = gOut + (size_t)b * 64 * NN + n0;
            #pragma unroll
            for (int i = tid; i < 2048; i += THREADS) {
                int o = i >> 5, j = i & 31;
                ob[(size_t)o * NN + j] = S.stg[o * 34 + j];
            }
        }
    }
}

extern "C" void kernel_launch(void* const* d_in, const int* in_sizes, int n_in,
                              void* d_out, int out_size) {
    (void)in_sizes; (void)n_in; (void)out_size;
    cudaFuncSetAttribute(pt_kernel, cudaFuncAttributeMaxDynamicSharedMemorySize,
                         (int)sizeof(Smem));
    pt_kernel<<<GRID, THREADS, sizeof(Smem)>>>(
        (const float*)d_in[0],  (const float*)d_in[1],  (const float*)d_in[2],
        (const float*)d_in[3],  (const float*)d_in[4],
        (const float*)d_in[5],  (const float*)d_in[6],
        (const float*)d_in[7],  (const float*)d_in[8],
        (const float*)d_in[9],  (const float*)d_in[10],
        (const float*)d_in[11], (const float*)d_in[12],
        (const float*)d_in[13], (const float*)d_in[14], (const float*)d_in[15],
        (const float*)d_in[16], (const float*)d_in[17],
        (float*)d_out);
}